// round 14
// baseline (speedup 1.0000x reference)
#include <cuda_runtime.h>
#include <cuda_fp16.h>
#include <math.h>
#include <stdint.h>

#define BATCH 16
#define LSEQ  1024
#define HDIM  1024

// -------------------- scratch (allocation-free) --------------------
__device__ __half g_hbf[(size_t)BATCH * LSEQ * HDIM];   // hidden fp16 [B*L, K]
__device__ __half g_w1t[(size_t)2048 * 1024];           // W1^T fp16 [N, K]
__device__ __half g_qc[(size_t)BATCH * LSEQ * HDIM];    // compacted q' fp16
__device__ __half g_kc[(size_t)BATCH * LSEQ * HDIM];    // compacted k' fp16
__device__ __half g_qk[(size_t)BATCH * LSEQ * LSEQ];    // compacted raw qk fp16 (32MB)
__device__ float  g_bias[BATCH * 4 * LSEQ];
__device__ int    g_idx[BATCH * LSEQ];                  // compact -> orig
__device__ int    g_rank[BATCH * LSEQ];                 // orig -> compact
__device__ int    g_cnt[BATCH];

// -------------------- helpers (baseline PTX ISA only) --------------------
__device__ __forceinline__ uint32_t smem_u32(const void* p) {
    uint32_t a;
    asm("{ .reg .u64 t; cvta.to.shared.u64 t, %1; cvt.u32.u64 %0, t; }" : "=r"(a) : "l"(p));
    return a;
}
__device__ __forceinline__ void cp16(uint32_t dst, const void* src) {
    asm volatile("cp.async.cg.shared.global [%0], [%1], 16;" :: "r"(dst), "l"(src));
}
__device__ __forceinline__ void cp_commit() { asm volatile("cp.async.commit_group;" ::: "memory"); }
__device__ __forceinline__ void ldsm4(uint32_t* r, uint32_t addr) {
    asm volatile("ldmatrix.sync.aligned.m8n8.x4.shared.b16 {%0,%1,%2,%3}, [%4];"
                 : "=r"(r[0]), "=r"(r[1]), "=r"(r[2]), "=r"(r[3]) : "r"(addr));
}
// f16-accumulate MMA: 2x rate, half the accumulator registers.
__device__ __forceinline__ void mma16816h(uint32_t* d, const uint32_t* a,
                                          uint32_t b0, uint32_t b1) {
    asm volatile("mma.sync.aligned.m16n8k16.row.col.f16.f16.f16.f16 "
                 "{%0,%1}, {%2,%3,%4,%5}, {%6,%7}, {%0,%1};"
                 : "+r"(d[0]), "+r"(d[1])
                 : "r"(a[0]), "r"(a[1]), "r"(a[2]), "r"(a[3]), "r"(b0), "r"(b1));
}

#define STAGE_BYTES 32768               // A 16KB + B 16KB per stage
#define DYN_SMEM    (1024 + 3 * STAGE_BYTES)

// -------------------- shared mainloop (R4 structure, f16 accum) -------------
// acc[mf][nf][h]: f16x2 = (col c, c+1) at row (r0 + h*8).
__device__ __forceinline__ void gemm_mainloop(const __half* __restrict__ ap,
                                              const __half* __restrict__ bp,
                                              uint32_t sb, uint32_t acc[4][4][2])
{
    const int tid = threadIdx.x, lane = tid & 31, wid = tid >> 5;
    const int wm = wid >> 2, wn = wid & 3;

    const int lrow = tid >> 1;
    const int lc0 = (tid & 1) * 4;
    uint32_t soff[4];
    #pragma unroll
    for (int i = 0; i < 4; ++i) {
        uint32_t off = lrow * 128 + (lc0 + i) * 16;
        soff[i] = off ^ ((off >> 3) & 0x70);
    }
    uint32_t stA[3], stB[3];
    #pragma unroll
    for (int s = 0; s < 3; ++s) { stA[s] = sb + s * STAGE_BYTES; stB[s] = stA[s] + 16384; }

    #pragma unroll
    for (int t = 0; t < 2; ++t) {
        #pragma unroll
        for (int i = 0; i < 4; ++i) {
            cp16(stA[t] + soff[i], ap + t * 64 + i * 8);
            cp16(stB[t] + soff[i], bp + t * 64 + i * 8);
        }
        cp_commit();
    }

    const int lr = lane & 15, lhi = lane >> 4;
    const uint32_t xorterm = (uint32_t)(lr & 7) * 16;
    uint32_t aRow[4], bRow[2];
    #pragma unroll
    for (int mf = 0; mf < 4; ++mf) aRow[mf] = (uint32_t)(wm * 64 + mf * 16 + lr) * 128;
    #pragma unroll
    for (int nfp = 0; nfp < 2; ++nfp) bRow[nfp] = (uint32_t)(wn * 32 + nfp * 16 + lr) * 128;

    #pragma unroll 1
    for (int kt = 0; kt < 16; ++kt) {
        if (kt == 15) asm volatile("cp.async.wait_group 0;" ::: "memory");
        else          asm volatile("cp.async.wait_group 1;" ::: "memory");
        __syncthreads();

        if (kt < 14) {
            const int t = kt + 2;
            const int sl = t - (t / 3) * 3;
            #pragma unroll
            for (int i = 0; i < 4; ++i) {
                cp16(stA[sl] + soff[i], ap + t * 64 + i * 8);
                cp16(stB[sl] + soff[i], bp + t * 64 + i * 8);
            }
            cp_commit();
        }

        const int s = kt - (kt / 3) * 3;
        const uint32_t sA = stA[s], sB = stB[s];
        #pragma unroll
        for (int ks = 0; ks < 4; ++ks) {
            const uint32_t colbyte = ((uint32_t)(ks * 2 + lhi) * 16) ^ xorterm;
            uint32_t bfr[2][4];
            #pragma unroll
            for (int nfp = 0; nfp < 2; ++nfp) ldsm4(bfr[nfp], sB + bRow[nfp] + colbyte);
            #pragma unroll
            for (int mf = 0; mf < 4; ++mf) {
                uint32_t afr[4];
                ldsm4(afr, sA + aRow[mf] + colbyte);
                #pragma unroll
                for (int nf = 0; nf < 4; ++nf)
                    mma16816h(acc[mf][nf], afr,
                              bfr[nf >> 1][nf & 1], bfr[nf >> 1][2 + (nf & 1)]);
            }
        }
    }
    __syncthreads();
}

// -------------------- compaction: per-batch prefix sum over tt --------------
__global__ __launch_bounds__(1024) void compact_kernel(const int* __restrict__ tt)
{
    __shared__ int sc[2][1024];
    const int b = blockIdx.x, j = threadIdx.x;
    const int v = tt[(b << 10) + j];
    sc[0][j] = v;
    __syncthreads();
    int cur = 0;
    #pragma unroll
    for (int d = 1; d < 1024; d <<= 1) {
        int x = sc[cur][j];
        if (j >= d) x += sc[cur][j - d];
        sc[cur ^ 1][j] = x;
        __syncthreads();
        cur ^= 1;
    }
    const int incl = sc[cur][j];
    const int rank = incl - v;
    const int cnt = sc[cur][1023];
    g_rank[(b << 10) + j] = rank;
    if (v) g_idx[(b << 10) + rank] = j;
    if (j >= cnt) g_idx[(b << 10) + j] = 0;
    if (j == 0) g_cnt[b] = cnt;
}

// -------------------- GEMM1c: compacted rows of hidden @ W1 + b1, RoPE ------
__global__ __launch_bounds__(256, 2) void gemm1_kernel(const float* __restrict__ b1v)
{
    extern __shared__ char smem_raw[];
    char* base = (char*)(((uintptr_t)smem_raw + 1023) & ~(uintptr_t)1023);
    const uint32_t sb = smem_u32(base);
    const int tid = threadIdx.x, lane = tid & 31, wid = tid >> 5;
    const int wm = wid >> 2, wn = wid & 3;
    const int b = blockIdx.z;
    const int m0 = blockIdx.y * 128, n0 = blockIdx.x * 128;
    if (m0 >= g_cnt[b]) return;

    const int lrow = tid >> 1, lc0 = (tid & 1) * 4;
    const int lorig = g_idx[(b << 10) + m0 + lrow];
    const __half* ap = g_hbf + ((size_t)(b << 10) + lorig) * 1024 + lc0 * 8;
    const __half* bp = g_w1t + (size_t)(n0 + lrow) * 1024 + lc0 * 8;

    uint32_t acc[4][4][2] = {};
    gemm_mainloop(ap, bp, sb, acc);

    // stage C tile to smem as fp16 [128][136] (stride 136 halves: conflict-free)
    __half* Cb = (__half*)base;
    const int r0 = wm * 64 + (lane >> 2);
    const int c0l = wn * 32 + (lane & 3) * 2;
    #pragma unroll
    for (int mf = 0; mf < 4; ++mf)
        #pragma unroll
        for (int nf = 0; nf < 4; ++nf) {
            __half* p = &Cb[(r0 + mf * 16) * 136 + c0l + nf * 8];
            *(uint32_t*)p             = acc[mf][nf][0];
            *(uint32_t*)(p + 8 * 136) = acc[mf][nf][1];
        }
    __syncthreads();

    // RoPE + scatter. Fixed quad per thread: __expf + b1 hoisted; __sincosf MUFU.
    const int quad = tid & 31;
    const int rgrp = tid >> 5;
    const int cb = n0 + quad * 4;
    const int ir = cb >> 2;
    const float inv = __expf(-(float)ir * (2.0f * 9.210340371976184f / 1024.0f));
    const float4 b1q = *(const float4*)&b1v[cb];

    #pragma unroll 1
    for (int it = 0; it < 16; ++it) {
        const int r = rgrp * 16 + it;
        uint2 vv = *(uint2*)&Cb[r * 136 + quad * 4];
        float2 p0 = __half22float2(*reinterpret_cast<__half2*>(&vv.x));
        float2 p1 = __half22float2(*reinterpret_cast<__half2*>(&vv.y));
        const int j = m0 + r;                    // compact row
        const int l = g_idx[(b << 10) + j];      // original position
        float s, c;
        __sincosf((float)l * inv, &s, &c);
        float q0 = p0.x + b1q.x;
        float k0 = p0.y + b1q.y;
        float q1 = p1.x + b1q.z;
        float k1 = p1.y + b1q.w;
        __half2 qh = __floats2half2_rn(q0 * c - q1 * s, q1 * c + q0 * s);
        __half2 kh = __floats2half2_rn(k0 * c - k1 * s, k1 * c + k0 * s);
        const size_t dst = ((size_t)(b << 10) + j) * 1024 + (cb >> 1);
        *(uint32_t*)&g_qc[dst] = *reinterpret_cast<uint32_t*>(&qh);
        *(uint32_t*)&g_kc[dst] = *reinterpret_cast<uint32_t*>(&kh);
    }
}

// -------------------- GEMM2c: compacted q' @ k'^T -> raw qk (fp16) ----------
__global__ __launch_bounds__(256, 2) void gemm2_kernel()
{
    extern __shared__ char smem_raw[];
    char* base = (char*)(((uintptr_t)smem_raw + 1023) & ~(uintptr_t)1023);
    const uint32_t sb = smem_u32(base);
    const int tid = threadIdx.x, lane = tid & 31, wid = tid >> 5;
    const int wm = wid >> 2, wn = wid & 3;
    const int b = blockIdx.z, m0 = blockIdx.y * 128, n0 = blockIdx.x * 128;
    const int c = g_cnt[b];
    if (m0 >= c || n0 >= c || m0 > n0 + 127) return;

    const int lrow = tid >> 1, lc0 = (tid & 1) * 4;
    const __half* ap = g_qc + ((size_t)(b << 10) + m0 + lrow) * 1024 + lc0 * 8;
    const __half* bp = g_kc + ((size_t)(b << 10) + n0 + lrow) * 1024 + lc0 * 8;

    uint32_t acc[4][4][2] = {};
    gemm_mainloop(ap, bp, sb, acc);

    #pragma unroll
    for (int mf = 0; mf < 4; ++mf)
        #pragma unroll
        for (int h = 0; h < 2; ++h) {
            const int Rl = wm * 64 + mf * 16 + (lane >> 2) + h * 8;
            __half* orow = g_qk + ((size_t)b << 20) + (size_t)(m0 + Rl) * 1024 + n0;
            #pragma unroll
            for (int nf = 0; nf < 4; ++nf) {
                const int Cl = wn * 32 + nf * 8 + (lane & 3) * 2;
                *(uint32_t*)(orow + Cl) = acc[mf][nf][h];
            }
        }
}

// -------------------- scatter/fill: produce full output ---------------------
// case table (bit-exact on constants; compute path error drowned by the norm):
//   unmasked & m<=n : qk/32 + bE + bO ; unmasked & m>n : -1e12f
//   masked   & m<=n : -1e12f          ; masked   & m>n : -2e12f
__global__ __launch_bounds__(256) void scatter_kernel(const int* __restrict__ tt,
                                                      float* __restrict__ out)
{
    const int b = blockIdx.y, m = blockIdx.x, tid = threadIdx.x;
    const int mr = tt[(b << 10) + m];
    const int rank_m = g_rank[(b << 10) + m];
    const float bo0 = g_bias[b * 4096 + 1024 + m];
    const float bo1 = g_bias[b * 4096 + 3072 + m];
    const __half* qrow = g_qk + ((size_t)b << 20) + (size_t)rank_m * 1024;
    float* o0 = out + ((size_t)(b * 2) << 20) + (size_t)m * 1024;
    float* o1 = o0 + (size_t)(1 << 20);

    const int n4 = tid * 4;
    const int4  mc4 = *(const int4*)&tt[(b << 10) + n4];
    const int4  rk4 = *(const int4*)&g_rank[(b << 10) + n4];
    const float4 be0 = *(const float4*)&g_bias[b * 4096 + n4];
    const float4 be1 = *(const float4*)&g_bias[b * 4096 + 2048 + n4];

    float4 v0, v1;
    const int mcs[4] = {mc4.x, mc4.y, mc4.z, mc4.w};
    const int rks[4] = {rk4.x, rk4.y, rk4.z, rk4.w};
    #pragma unroll
    for (int e = 0; e < 4; ++e) {
        const int n = n4 + e;
        const bool um = (mr != 0) && (mcs[e] != 0);
        if (um && m <= n) {
            const float qk = __half2float(qrow[rks[e]]);
            (&v0.x)[e] = fmaf(qk, 0.03125f, (&be0.x)[e]) + bo0;
            (&v1.x)[e] = fmaf(qk, 0.03125f, (&be1.x)[e]) + bo1;
        } else {
            const float f = (m > n && !um) ? -2e12f : -1e12f;
            (&v0.x)[e] = f;
            (&v1.x)[e] = f;
        }
    }
    *(float4*)(o0 + n4) = v0;
    *(float4*)(o1 + n4) = v1;
}

// -------------------- prep: fused hidden->fp16 convert + bias GEMV ----------
__global__ __launch_bounds__(256) void prep_hidden(const float* __restrict__ hidden,
                                                   const float* __restrict__ W2,
                                                   const float* __restrict__ b2)
{
    const int wid = threadIdx.x >> 5, lane = threadIdx.x & 31;
    const int row = blockIdx.x * 8 + wid;
    const float* h = hidden + (size_t)row * 1024;
    __half* o = g_hbf + (size_t)row * 1024;
    float a0 = 0.f, a1 = 0.f, a2 = 0.f, a3 = 0.f;
    #pragma unroll
    for (int i = 0; i < 8; ++i) {
        const int c4 = i * 32 + lane;
        float4 v = *(const float4*)&h[c4 * 4];
        __half2 h0 = __floats2half2_rn(v.x, v.y);
        __half2 h1 = __floats2half2_rn(v.z, v.w);
        uint2 st;
        st.x = *reinterpret_cast<uint32_t*>(&h0);
        st.y = *reinterpret_cast<uint32_t*>(&h1);
        *(uint2*)&o[c4 * 4] = st;
        const int k = c4 * 4;
        float4 w0 = *(const float4*)&W2[(k + 0) * 4];
        float4 w1 = *(const float4*)&W2[(k + 1) * 4];
        float4 w2 = *(const float4*)&W2[(k + 2) * 4];
        float4 w3 = *(const float4*)&W2[(k + 3) * 4];
        a0 += v.x * w0.x + v.y * w1.x + v.z * w2.x + v.w * w3.x;
        a1 += v.x * w0.y + v.y * w1.y + v.z * w2.y + v.w * w3.y;
        a2 += v.x * w0.z + v.y * w1.z + v.z * w2.z + v.w * w3.z;
        a3 += v.x * w0.w + v.y * w1.w + v.z * w2.w + v.w * w3.w;
    }
    #pragma unroll
    for (int off = 16; off > 0; off >>= 1) {
        a0 += __shfl_xor_sync(0xFFFFFFFF, a0, off);
        a1 += __shfl_xor_sync(0xFFFFFFFF, a1, off);
        a2 += __shfl_xor_sync(0xFFFFFFFF, a2, off);
        a3 += __shfl_xor_sync(0xFFFFFFFF, a3, off);
    }
    if (lane == 0) {
        const int bb = row >> 10, l = row & 1023;
        float* bp = g_bias + (size_t)bb * 4096 + l;
        bp[0]    = (a0 + b2[0]) * 0.5f;
        bp[1024] = (a1 + b2[1]) * 0.5f;
        bp[2048] = (a2 + b2[2]) * 0.5f;
        bp[3072] = (a3 + b2[3]) * 0.5f;
    }
}

__global__ __launch_bounds__(256) void transpose_w1(const float* __restrict__ W1)
{
    __shared__ float tile[32][33];
    const int tx = threadIdx.x & 31, ty = threadIdx.x >> 5;
    const int nb = blockIdx.x * 32, kb = blockIdx.y * 32;
    #pragma unroll
    for (int i = 0; i < 4; ++i)
        tile[ty + i * 8][tx] = W1[(size_t)(kb + ty + i * 8) * 2048 + nb + tx];
    __syncthreads();
    #pragma unroll
    for (int i = 0; i < 4; ++i)
        g_w1t[(size_t)(nb + ty + i * 8) * 1024 + kb + tx] = __float2half_rn(tile[tx][ty + i * 8]);
}

// -------------------- launch --------------------
extern "C" void kernel_launch(void* const* d_in, const int* in_sizes, int n_in,
                              void* d_out, int out_size)
{
    const float* hidden = (const float*)d_in[0];
    const int*   tt     = (const int*)d_in[1];
    const float* W1     = (const float*)d_in[2];
    const float* b1     = (const float*)d_in[3];
    const float* W2     = (const float*)d_in[4];
    const float* b2     = (const float*)d_in[5];
    float* out = (float*)d_out;

    cudaFuncSetAttribute(gemm1_kernel, cudaFuncAttributeMaxDynamicSharedMemorySize, DYN_SMEM);
    cudaFuncSetAttribute(gemm2_kernel, cudaFuncAttributeMaxDynamicSharedMemorySize, DYN_SMEM);

    compact_kernel<<<BATCH, 1024>>>(tt);
    prep_hidden<<<2048, 256>>>(hidden, W2, b2);
    transpose_w1<<<dim3(64, 32), dim3(256)>>>(W1);

    dim3 g1(16, 8, BATCH);            // N/128 x Mc-tiles x B (early-exit on cnt)
    gemm1_kernel<<<g1, 256, DYN_SMEM>>>(b1);

    dim3 g2(8, 8, BATCH);             // Nc x Mc x B (early-exit on cnt/triangle)
    gemm2_kernel<<<g2, 256, DYN_SMEM>>>();

    dim3 gs(LSEQ, BATCH);             // one block per output row
    scatter_kernel<<<gs, 256>>>(tt, out);
}

// round 15
// speedup vs baseline: 1.5116x; 1.5116x over previous
#include <cuda_runtime.h>
#include <cuda_fp16.h>
#include <math.h>
#include <stdint.h>

#define BATCH 16
#define LSEQ  1024
#define HDIM  1024

// -------------------- scratch (allocation-free) --------------------
__device__ __half g_hbf[(size_t)BATCH * LSEQ * HDIM];   // hidden fp16 [B*L, K]
__device__ __half g_w1t[(size_t)2048 * 1024];           // W1^T fp16 [N, K]
__device__ __half g_qc[(size_t)BATCH * LSEQ * HDIM];    // compacted q' fp16
__device__ __half g_kc[(size_t)BATCH * LSEQ * HDIM];    // compacted k' fp16
__device__ float  g_qk[(size_t)BATCH * LSEQ * LSEQ];    // compacted raw qk (64MB)
__device__ float  g_bias[BATCH * 4 * LSEQ];
__device__ int    g_idx[BATCH * LSEQ];                  // compact -> orig
__device__ int    g_rank[BATCH * LSEQ];                 // orig -> compact
__device__ int    g_cnt[BATCH];

// -------------------- helpers (baseline PTX ISA only) --------------------
__device__ __forceinline__ uint32_t smem_u32(const void* p) {
    uint32_t a;
    asm("{ .reg .u64 t; cvta.to.shared.u64 t, %1; cvt.u32.u64 %0, t; }" : "=r"(a) : "l"(p));
    return a;
}
__device__ __forceinline__ void cp16(uint32_t dst, const void* src) {
    asm volatile("cp.async.cg.shared.global [%0], [%1], 16;" :: "r"(dst), "l"(src));
}
__device__ __forceinline__ void cp_commit() { asm volatile("cp.async.commit_group;" ::: "memory"); }
__device__ __forceinline__ void ldsm4(uint32_t* r, uint32_t addr) {
    asm volatile("ldmatrix.sync.aligned.m8n8.x4.shared.b16 {%0,%1,%2,%3}, [%4];"
                 : "=r"(r[0]), "=r"(r[1]), "=r"(r[2]), "=r"(r[3]) : "r"(addr));
}
__device__ __forceinline__ void mma16816(float* d, const uint32_t* a, uint32_t b0, uint32_t b1) {
    asm volatile("mma.sync.aligned.m16n8k16.row.col.f32.f16.f16.f32 "
                 "{%0,%1,%2,%3}, {%4,%5,%6,%7}, {%8,%9}, {%0,%1,%2,%3};"
                 : "+f"(d[0]), "+f"(d[1]), "+f"(d[2]), "+f"(d[3])
                 : "r"(a[0]), "r"(a[1]), "r"(a[2]), "r"(a[3]), "r"(b0), "r"(b1));
}

#define STAGE_BYTES 32768               // gemm1: A 16KB + B 16KB per stage
#define DYN_SMEM    (1024 + 3 * STAGE_BYTES)
#define G2_STAGE    16384               // gemm2: A 8KB + B 8KB per stage
#define DYN_SMEM2   (1024 + 3 * G2_STAGE)

// -------------------- 128x128 mainloop, fp32 accum (R12 — measured best) ----
__device__ __forceinline__ void gemm_mainloop(const __half* __restrict__ ap,
                                              const __half* __restrict__ bp,
                                              uint32_t sb, float acc[4][4][4])
{
    const int tid = threadIdx.x, lane = tid & 31, wid = tid >> 5;
    const int wm = wid >> 2, wn = wid & 3;

    const int lrow = tid >> 1;
    const int lc0 = (tid & 1) * 4;
    uint32_t soff[4];
    #pragma unroll
    for (int i = 0; i < 4; ++i) {
        uint32_t off = lrow * 128 + (lc0 + i) * 16;
        soff[i] = off ^ ((off >> 3) & 0x70);
    }
    uint32_t stA[3], stB[3];
    #pragma unroll
    for (int s = 0; s < 3; ++s) { stA[s] = sb + s * STAGE_BYTES; stB[s] = stA[s] + 16384; }

    #pragma unroll
    for (int t = 0; t < 2; ++t) {
        #pragma unroll
        for (int i = 0; i < 4; ++i) {
            cp16(stA[t] + soff[i], ap + t * 64 + i * 8);
            cp16(stB[t] + soff[i], bp + t * 64 + i * 8);
        }
        cp_commit();
    }

    const int lr = lane & 15, lhi = lane >> 4;
    const uint32_t xorterm = (uint32_t)(lr & 7) * 16;
    uint32_t aRow[4], bRow[2];
    #pragma unroll
    for (int mf = 0; mf < 4; ++mf) aRow[mf] = (uint32_t)(wm * 64 + mf * 16 + lr) * 128;
    #pragma unroll
    for (int nfp = 0; nfp < 2; ++nfp) bRow[nfp] = (uint32_t)(wn * 32 + nfp * 16 + lr) * 128;

    #pragma unroll 1
    for (int kt = 0; kt < 16; ++kt) {
        if (kt == 15) asm volatile("cp.async.wait_group 0;" ::: "memory");
        else          asm volatile("cp.async.wait_group 1;" ::: "memory");
        __syncthreads();

        if (kt < 14) {
            const int t = kt + 2;
            const int sl = t - (t / 3) * 3;
            #pragma unroll
            for (int i = 0; i < 4; ++i) {
                cp16(stA[sl] + soff[i], ap + t * 64 + i * 8);
                cp16(stB[sl] + soff[i], bp + t * 64 + i * 8);
            }
            cp_commit();
        }

        const int s = kt - (kt / 3) * 3;
        const uint32_t sA = stA[s], sB = stB[s];
        #pragma unroll
        for (int ks = 0; ks < 4; ++ks) {
            const uint32_t colbyte = ((uint32_t)(ks * 2 + lhi) * 16) ^ xorterm;
            uint32_t bfr[2][4];
            #pragma unroll
            for (int nfp = 0; nfp < 2; ++nfp) ldsm4(bfr[nfp], sB + bRow[nfp] + colbyte);
            #pragma unroll
            for (int mf = 0; mf < 4; ++mf) {
                uint32_t afr[4];
                ldsm4(afr, sA + aRow[mf] + colbyte);
                #pragma unroll
                for (int nf = 0; nf < 4; ++nf)
                    mma16816(acc[mf][nf], afr,
                             bfr[nf >> 1][nf & 1], bfr[nf >> 1][2 + (nf & 1)]);
            }
        }
    }
    __syncthreads();
}

// -------------------- compaction: per-batch prefix sum over tt --------------
__global__ __launch_bounds__(1024) void compact_kernel(const int* __restrict__ tt)
{
    __shared__ int sc[2][1024];
    const int b = blockIdx.x, j = threadIdx.x;
    const int v = tt[(b << 10) + j];
    sc[0][j] = v;
    __syncthreads();
    int cur = 0;
    #pragma unroll
    for (int d = 1; d < 1024; d <<= 1) {
        int x = sc[cur][j];
        if (j >= d) x += sc[cur][j - d];
        sc[cur ^ 1][j] = x;
        __syncthreads();
        cur ^= 1;
    }
    const int incl = sc[cur][j];
    const int rank = incl - v;
    const int cnt = sc[cur][1023];
    g_rank[(b << 10) + j] = rank;
    if (v) g_idx[(b << 10) + rank] = j;
    if (j >= cnt) g_idx[(b << 10) + j] = 0;
    if (j == 0) g_cnt[b] = cnt;
}

// -------------------- GEMM1c: compacted rows of hidden @ W1 + b1, RoPE ------
__global__ __launch_bounds__(256, 2) void gemm1_kernel(const float* __restrict__ b1v)
{
    extern __shared__ char smem_raw[];
    char* base = (char*)(((uintptr_t)smem_raw + 1023) & ~(uintptr_t)1023);
    const uint32_t sb = smem_u32(base);
    const int tid = threadIdx.x, lane = tid & 31, wid = tid >> 5;
    const int wm = wid >> 2, wn = wid & 3;
    const int b = blockIdx.z;
    const int m0 = blockIdx.y * 128, n0 = blockIdx.x * 128;
    if (m0 >= g_cnt[b]) return;

    const int lrow = tid >> 1, lc0 = (tid & 1) * 4;
    const int lorig = g_idx[(b << 10) + m0 + lrow];
    const __half* ap = g_hbf + ((size_t)(b << 10) + lorig) * 1024 + lc0 * 8;
    const __half* bp = g_w1t + (size_t)(n0 + lrow) * 1024 + lc0 * 8;

    float acc[4][4][4] = {};
    gemm_mainloop(ap, bp, sb, acc);

    float* Cb = (float*)base;      // [128][132]
    const int r0 = wm * 64 + (lane >> 2);
    const int c0l = wn * 32 + (lane & 3) * 2;
    #pragma unroll
    for (int mf = 0; mf < 4; ++mf)
        #pragma unroll
        for (int nf = 0; nf < 4; ++nf) {
            float* p = &Cb[(r0 + mf * 16) * 132 + c0l + nf * 8];
            *(float2*)p             = make_float2(acc[mf][nf][0], acc[mf][nf][1]);
            *(float2*)(p + 8 * 132) = make_float2(acc[mf][nf][2], acc[mf][nf][3]);
        }
    __syncthreads();

    // RoPE + scatter. Fixed quad per thread: __expf + b1 hoisted; __sincosf MUFU.
    const int quad = tid & 31;
    const int rgrp = tid >> 5;
    const int cb = n0 + quad * 4;
    const int ir = cb >> 2;
    const float inv = __expf(-(float)ir * (2.0f * 9.210340371976184f / 1024.0f));
    const float4 b1q = *(const float4*)&b1v[cb];

    #pragma unroll 1
    for (int it = 0; it < 16; ++it) {
        const int r = rgrp * 16 + it;
        float4 v = *(float4*)&Cb[r * 132 + quad * 4];
        const int j = m0 + r;                    // compact row
        const int l = g_idx[(b << 10) + j];      // original position
        float s, c;
        __sincosf((float)l * inv, &s, &c);
        float q0 = v.x + b1q.x;
        float k0 = v.y + b1q.y;
        float q1 = v.z + b1q.z;
        float k1 = v.w + b1q.w;
        __half2 qh = __floats2half2_rn(q0 * c - q1 * s, q1 * c + q0 * s);
        __half2 kh = __floats2half2_rn(k0 * c - k1 * s, k1 * c + k0 * s);
        const size_t dst = ((size_t)(b << 10) + j) * 1024 + (cb >> 1);
        *(uint32_t*)&g_qc[dst] = *reinterpret_cast<uint32_t*>(&qh);
        *(uint32_t*)&g_kc[dst] = *reinterpret_cast<uint32_t*>(&kh);
    }
}

// -------------------- GEMM2c: 64x64 tiles, dense triangular enumeration -----
// 128 threads, 4 warps (2m x 2n), warp tile 32x32. 4 CTAs/SM -> full wave.
__global__ __launch_bounds__(128, 4) void gemm2_kernel()
{
    extern __shared__ char smem_raw[];
    char* base = (char*)(((uintptr_t)smem_raw + 1023) & ~(uintptr_t)1023);
    const uint32_t sb = smem_u32(base);
    const int tid = threadIdx.x, lane = tid & 31, wid = tid >> 5;
    const int wm = wid >> 1, wn = wid & 1;
    const int b = blockIdx.y;

    // triangular map: t -> (mi <= ni); covers all tiles intersecting m <= n
    const int t = blockIdx.x;
    int ni = 0;
    while ((ni + 1) * (ni + 2) / 2 <= t) ++ni;
    const int mi = t - ni * (ni + 1) / 2;
    const int m0 = mi * 64, n0 = ni * 64;
    const int c = g_cnt[b];
    if (m0 >= c || n0 >= c) return;

    const int lrow = tid >> 1, lc0 = (tid & 1) * 4;
    const __half* ap = g_qc + ((size_t)(b << 10) + m0 + lrow) * 1024 + lc0 * 8;
    const __half* bp = g_kc + ((size_t)(b << 10) + n0 + lrow) * 1024 + lc0 * 8;
    uint32_t soff[4];
    #pragma unroll
    for (int i = 0; i < 4; ++i) {
        uint32_t off = lrow * 128 + (lc0 + i) * 16;
        soff[i] = off ^ ((off >> 3) & 0x70);
    }
    uint32_t stA[3], stB[3];
    #pragma unroll
    for (int s = 0; s < 3; ++s) { stA[s] = sb + s * G2_STAGE; stB[s] = stA[s] + 8192; }

    #pragma unroll
    for (int tpre = 0; tpre < 2; ++tpre) {
        #pragma unroll
        for (int i = 0; i < 4; ++i) {
            cp16(stA[tpre] + soff[i], ap + tpre * 64 + i * 8);
            cp16(stB[tpre] + soff[i], bp + tpre * 64 + i * 8);
        }
        cp_commit();
    }

    const int lr = lane & 15, lhi = lane >> 4;
    const uint32_t xorterm = (uint32_t)(lr & 7) * 16;
    uint32_t aRow[2], bRow[2];
    #pragma unroll
    for (int mf = 0; mf < 2; ++mf) aRow[mf] = (uint32_t)(wm * 32 + mf * 16 + lr) * 128;
    #pragma unroll
    for (int nfp = 0; nfp < 2; ++nfp) bRow[nfp] = (uint32_t)(wn * 32 + nfp * 16 + lr) * 128;

    float acc[2][4][4] = {};

    #pragma unroll 1
    for (int kt = 0; kt < 16; ++kt) {
        if (kt == 15) asm volatile("cp.async.wait_group 0;" ::: "memory");
        else          asm volatile("cp.async.wait_group 1;" ::: "memory");
        __syncthreads();

        if (kt < 14) {
            const int tp = kt + 2;
            const int sl = tp - (tp / 3) * 3;
            #pragma unroll
            for (int i = 0; i < 4; ++i) {
                cp16(stA[sl] + soff[i], ap + tp * 64 + i * 8);
                cp16(stB[sl] + soff[i], bp + tp * 64 + i * 8);
            }
            cp_commit();
        }

        const int s = kt - (kt / 3) * 3;
        const uint32_t sA = stA[s], sB = stB[s];
        #pragma unroll
        for (int ks = 0; ks < 4; ++ks) {
            const uint32_t colbyte = ((uint32_t)(ks * 2 + lhi) * 16) ^ xorterm;
            uint32_t bfr[2][4];
            #pragma unroll
            for (int nfp = 0; nfp < 2; ++nfp) ldsm4(bfr[nfp], sB + bRow[nfp] + colbyte);
            #pragma unroll
            for (int mf = 0; mf < 2; ++mf) {
                uint32_t afr[4];
                ldsm4(afr, sA + aRow[mf] + colbyte);
                #pragma unroll
                for (int nf = 0; nf < 4; ++nf)
                    mma16816(acc[mf][nf], afr,
                             bfr[nf >> 1][nf & 1], bfr[nf >> 1][2 + (nf & 1)]);
            }
        }
    }

    #pragma unroll
    for (int mf = 0; mf < 2; ++mf)
        #pragma unroll
        for (int h = 0; h < 2; ++h) {
            const int Rl = wm * 32 + mf * 16 + (lane >> 2) + h * 8;
            float* orow = g_qk + ((size_t)b << 20) + (size_t)(m0 + Rl) * 1024 + n0;
            #pragma unroll
            for (int nf = 0; nf < 4; ++nf) {
                const int Cl = wn * 32 + nf * 8 + (lane & 3) * 2;
                *(float2*)(orow + Cl) =
                    make_float2(acc[mf][nf][h * 2], acc[mf][nf][h * 2 + 1]);
            }
        }
}

// -------------------- scatter/fill: produce full output ---------------------
// case table (bit-exact vs fp32 reference, since |qk/32+biases| << ulp(1e12)):
//   unmasked & m<=n : qk/32 + bE + bO ; unmasked & m>n : -1e12f
//   masked   & m<=n : -1e12f          ; masked   & m>n : -2e12f
__global__ __launch_bounds__(256) void scatter_kernel(const int* __restrict__ tt,
                                                      float* __restrict__ out)
{
    const int b = blockIdx.y, m = blockIdx.x, tid = threadIdx.x;
    const int mr = tt[(b << 10) + m];
    const int rank_m = g_rank[(b << 10) + m];
    const float bo0 = g_bias[b * 4096 + 1024 + m];
    const float bo1 = g_bias[b * 4096 + 3072 + m];
    const float* qrow = g_qk + ((size_t)b << 20) + (size_t)rank_m * 1024;
    float* o0 = out + ((size_t)(b * 2) << 20) + (size_t)m * 1024;
    float* o1 = o0 + (size_t)(1 << 20);

    const int n4 = tid * 4;
    const int4  mc4 = *(const int4*)&tt[(b << 10) + n4];
    const int4  rk4 = *(const int4*)&g_rank[(b << 10) + n4];
    const float4 be0 = *(const float4*)&g_bias[b * 4096 + n4];
    const float4 be1 = *(const float4*)&g_bias[b * 4096 + 2048 + n4];

    float4 v0, v1;
    const int mcs[4] = {mc4.x, mc4.y, mc4.z, mc4.w};
    const int rks[4] = {rk4.x, rk4.y, rk4.z, rk4.w};
    #pragma unroll
    for (int e = 0; e < 4; ++e) {
        const int n = n4 + e;
        const bool um = (mr != 0) && (mcs[e] != 0);
        if (um && m <= n) {
            const float qk = qrow[rks[e]];
            (&v0.x)[e] = fmaf(qk, 0.03125f, (&be0.x)[e]) + bo0;
            (&v1.x)[e] = fmaf(qk, 0.03125f, (&be1.x)[e]) + bo1;
        } else {
            const float f = (m > n && !um) ? -2e12f : -1e12f;
            (&v0.x)[e] = f;
            (&v1.x)[e] = f;
        }
    }
    *(float4*)(o0 + n4) = v0;
    *(float4*)(o1 + n4) = v1;
}

// -------------------- prep: fused hidden->fp16 convert + bias GEMV ----------
__global__ __launch_bounds__(256) void prep_hidden(const float* __restrict__ hidden,
                                                   const float* __restrict__ W2,
                                                   const float* __restrict__ b2)
{
    const int wid = threadIdx.x >> 5, lane = threadIdx.x & 31;
    const int row = blockIdx.x * 8 + wid;
    const float* h = hidden + (size_t)row * 1024;
    __half* o = g_hbf + (size_t)row * 1024;
    float a0 = 0.f, a1 = 0.f, a2 = 0.f, a3 = 0.f;
    #pragma unroll
    for (int i = 0; i < 8; ++i) {
        const int c4 = i * 32 + lane;
        float4 v = *(const float4*)&h[c4 * 4];
        __half2 h0 = __floats2half2_rn(v.x, v.y);
        __half2 h1 = __floats2half2_rn(v.z, v.w);
        uint2 st;
        st.x = *reinterpret_cast<uint32_t*>(&h0);
        st.y = *reinterpret_cast<uint32_t*>(&h1);
        *(uint2*)&o[c4 * 4] = st;
        const int k = c4 * 4;
        float4 w0 = *(const float4*)&W2[(k + 0) * 4];
        float4 w1 = *(const float4*)&W2[(k + 1) * 4];
        float4 w2 = *(const float4*)&W2[(k + 2) * 4];
        float4 w3 = *(const float4*)&W2[(k + 3) * 4];
        a0 += v.x * w0.x + v.y * w1.x + v.z * w2.x + v.w * w3.x;
        a1 += v.x * w0.y + v.y * w1.y + v.z * w2.y + v.w * w3.y;
        a2 += v.x * w0.z + v.y * w1.z + v.z * w2.z + v.w * w3.z;
        a3 += v.x * w0.w + v.y * w1.w + v.z * w2.w + v.w * w3.w;
    }
    #pragma unroll
    for (int off = 16; off > 0; off >>= 1) {
        a0 += __shfl_xor_sync(0xFFFFFFFF, a0, off);
        a1 += __shfl_xor_sync(0xFFFFFFFF, a1, off);
        a2 += __shfl_xor_sync(0xFFFFFFFF, a2, off);
        a3 += __shfl_xor_sync(0xFFFFFFFF, a3, off);
    }
    if (lane == 0) {
        const int bb = row >> 10, l = row & 1023;
        float* bp = g_bias + (size_t)bb * 4096 + l;
        bp[0]    = (a0 + b2[0]) * 0.5f;
        bp[1024] = (a1 + b2[1]) * 0.5f;
        bp[2048] = (a2 + b2[2]) * 0.5f;
        bp[3072] = (a3 + b2[3]) * 0.5f;
    }
}

__global__ __launch_bounds__(256) void transpose_w1(const float* __restrict__ W1)
{
    __shared__ float tile[32][33];
    const int tx = threadIdx.x & 31, ty = threadIdx.x >> 5;
    const int nb = blockIdx.x * 32, kb = blockIdx.y * 32;
    #pragma unroll
    for (int i = 0; i < 4; ++i)
        tile[ty + i * 8][tx] = W1[(size_t)(kb + ty + i * 8) * 2048 + nb + tx];
    __syncthreads();
    #pragma unroll
    for (int i = 0; i < 4; ++i)
        g_w1t[(size_t)(nb + ty + i * 8) * 1024 + kb + tx] = __float2half_rn(tile[tx][ty + i * 8]);
}

// -------------------- launch --------------------
extern "C" void kernel_launch(void* const* d_in, const int* in_sizes, int n_in,
                              void* d_out, int out_size)
{
    const float* hidden = (const float*)d_in[0];
    const int*   tt     = (const int*)d_in[1];
    const float* W1     = (const float*)d_in[2];
    const float* b1     = (const float*)d_in[3];
    const float* W2     = (const float*)d_in[4];
    const float* b2     = (const float*)d_in[5];
    float* out = (float*)d_out;

    cudaFuncSetAttribute(gemm1_kernel, cudaFuncAttributeMaxDynamicSharedMemorySize, DYN_SMEM);
    cudaFuncSetAttribute(gemm2_kernel, cudaFuncAttributeMaxDynamicSharedMemorySize, DYN_SMEM2);

    compact_kernel<<<BATCH, 1024>>>(tt);
    prep_hidden<<<2048, 256>>>(hidden, W2, b2);
    transpose_w1<<<dim3(64, 32), dim3(256)>>>(W1);

    dim3 g1(16, 8, BATCH);            // N/128 x Mc-tiles x B (early-exit on cnt)
    gemm1_kernel<<<g1, 256, DYN_SMEM>>>(b1);

    dim3 g2(45, BATCH);               // triangular 64x64 tiles (exit on cnt)
    gemm2_kernel<<<g2, 128, DYN_SMEM2>>>();

    dim3 gs(LSEQ, BATCH);             // one block per output row
    scatter_kernel<<<gs, 256>>>(tt, out);
}

// round 16
// speedup vs baseline: 1.5201x; 1.0056x over previous
#include <cuda_runtime.h>
#include <cuda_fp16.h>
#include <math.h>
#include <stdint.h>

#define BATCH 16
#define LSEQ  1024
#define HDIM  1024

// -------------------- scratch (allocation-free) --------------------
__device__ __half g_hbf[(size_t)BATCH * LSEQ * HDIM];   // hidden fp16 [B*L, K]
__device__ __half g_w1t[(size_t)2048 * 1024];           // W1^T fp16 [N, K]
__device__ __half g_qc[(size_t)BATCH * LSEQ * HDIM];    // compacted q' fp16
__device__ __half g_kc[(size_t)BATCH * LSEQ * HDIM];    // compacted k' fp16
__device__ float  g_qk[(size_t)BATCH * LSEQ * LSEQ];    // compacted raw qk (64MB)
__device__ float  g_bias[BATCH * 4 * LSEQ];
__device__ int    g_idx[BATCH * LSEQ];                  // compact -> orig (unmasked)
__device__ int    g_midx[BATCH * LSEQ];                 // masked-compact -> orig
__device__ int    g_rank[BATCH * LSEQ];                 // orig -> compact
__device__ int    g_cnt[BATCH];

// -------------------- helpers (baseline PTX ISA only) --------------------
__device__ __forceinline__ uint32_t smem_u32(const void* p) {
    uint32_t a;
    asm("{ .reg .u64 t; cvta.to.shared.u64 t, %1; cvt.u32.u64 %0, t; }" : "=r"(a) : "l"(p));
    return a;
}
__device__ __forceinline__ void cp16(uint32_t dst, const void* src) {
    asm volatile("cp.async.cg.shared.global [%0], [%1], 16;" :: "r"(dst), "l"(src));
}
__device__ __forceinline__ void cp_commit() { asm volatile("cp.async.commit_group;" ::: "memory"); }
__device__ __forceinline__ void ldsm4(uint32_t* r, uint32_t addr) {
    asm volatile("ldmatrix.sync.aligned.m8n8.x4.shared.b16 {%0,%1,%2,%3}, [%4];"
                 : "=r"(r[0]), "=r"(r[1]), "=r"(r[2]), "=r"(r[3]) : "r"(addr));
}
__device__ __forceinline__ void mma16816(float* d, const uint32_t* a, uint32_t b0, uint32_t b1) {
    asm volatile("mma.sync.aligned.m16n8k16.row.col.f32.f16.f16.f32 "
                 "{%0,%1,%2,%3}, {%4,%5,%6,%7}, {%8,%9}, {%0,%1,%2,%3};"
                 : "+f"(d[0]), "+f"(d[1]), "+f"(d[2]), "+f"(d[3])
                 : "r"(a[0]), "r"(a[1]), "r"(a[2]), "r"(a[3]), "r"(b0), "r"(b1));
}
// streaming store: out is write-once; keep it out of L2 (protects qk residency)
__device__ __forceinline__ void stcs4(float* p, float4 v) {
    asm volatile("st.global.cs.v4.f32 [%0], {%1,%2,%3,%4};"
                 :: "l"(p), "f"(v.x), "f"(v.y), "f"(v.z), "f"(v.w) : "memory");
}

#define STAGE_BYTES 32768               // gemm1: A 16KB + B 16KB per stage
#define DYN_SMEM    (1024 + 3 * STAGE_BYTES)
#define G2_STAGE    16384               // gemm2: A 8KB + B 8KB per stage
#define DYN_SMEM2   (1024 + 3 * G2_STAGE)

// -------------------- 128x128 mainloop, fp32 accum (measured best) ----------
__device__ __forceinline__ void gemm_mainloop(const __half* __restrict__ ap,
                                              const __half* __restrict__ bp,
                                              uint32_t sb, float acc[4][4][4])
{
    const int tid = threadIdx.x, lane = tid & 31, wid = tid >> 5;
    const int wm = wid >> 2, wn = wid & 3;

    const int lrow = tid >> 1;
    const int lc0 = (tid & 1) * 4;
    uint32_t soff[4];
    #pragma unroll
    for (int i = 0; i < 4; ++i) {
        uint32_t off = lrow * 128 + (lc0 + i) * 16;
        soff[i] = off ^ ((off >> 3) & 0x70);
    }
    uint32_t stA[3], stB[3];
    #pragma unroll
    for (int s = 0; s < 3; ++s) { stA[s] = sb + s * STAGE_BYTES; stB[s] = stA[s] + 16384; }

    #pragma unroll
    for (int t = 0; t < 2; ++t) {
        #pragma unroll
        for (int i = 0; i < 4; ++i) {
            cp16(stA[t] + soff[i], ap + t * 64 + i * 8);
            cp16(stB[t] + soff[i], bp + t * 64 + i * 8);
        }
        cp_commit();
    }

    const int lr = lane & 15, lhi = lane >> 4;
    const uint32_t xorterm = (uint32_t)(lr & 7) * 16;
    uint32_t aRow[4], bRow[2];
    #pragma unroll
    for (int mf = 0; mf < 4; ++mf) aRow[mf] = (uint32_t)(wm * 64 + mf * 16 + lr) * 128;
    #pragma unroll
    for (int nfp = 0; nfp < 2; ++nfp) bRow[nfp] = (uint32_t)(wn * 32 + nfp * 16 + lr) * 128;

    #pragma unroll 1
    for (int kt = 0; kt < 16; ++kt) {
        if (kt == 15) asm volatile("cp.async.wait_group 0;" ::: "memory");
        else          asm volatile("cp.async.wait_group 1;" ::: "memory");
        __syncthreads();

        if (kt < 14) {
            const int t = kt + 2;
            const int sl = t - (t / 3) * 3;
            #pragma unroll
            for (int i = 0; i < 4; ++i) {
                cp16(stA[sl] + soff[i], ap + t * 64 + i * 8);
                cp16(stB[sl] + soff[i], bp + t * 64 + i * 8);
            }
            cp_commit();
        }

        const int s = kt - (kt / 3) * 3;
        const uint32_t sA = stA[s], sB = stB[s];
        #pragma unroll
        for (int ks = 0; ks < 4; ++ks) {
            const uint32_t colbyte = ((uint32_t)(ks * 2 + lhi) * 16) ^ xorterm;
            uint32_t bfr[2][4];
            #pragma unroll
            for (int nfp = 0; nfp < 2; ++nfp) ldsm4(bfr[nfp], sB + bRow[nfp] + colbyte);
            #pragma unroll
            for (int mf = 0; mf < 4; ++mf) {
                uint32_t afr[4];
                ldsm4(afr, sA + aRow[mf] + colbyte);
                #pragma unroll
                for (int nf = 0; nf < 4; ++nf)
                    mma16816(acc[mf][nf], afr,
                             bfr[nf >> 1][nf & 1], bfr[nf >> 1][2 + (nf & 1)]);
            }
        }
    }
    __syncthreads();
}

// -------------------- compaction: per-batch prefix sum over tt --------------
__global__ __launch_bounds__(1024) void compact_kernel(const int* __restrict__ tt)
{
    __shared__ int sc[2][1024];
    const int b = blockIdx.x, j = threadIdx.x;
    const int v = tt[(b << 10) + j];
    sc[0][j] = v;
    __syncthreads();
    int cur = 0;
    #pragma unroll
    for (int d = 1; d < 1024; d <<= 1) {
        int x = sc[cur][j];
        if (j >= d) x += sc[cur][j - d];
        sc[cur ^ 1][j] = x;
        __syncthreads();
        cur ^= 1;
    }
    const int incl = sc[cur][j];
    const int rank = incl - v;
    const int cnt = sc[cur][1023];
    g_rank[(b << 10) + j] = rank;
    if (v) g_idx[(b << 10) + rank] = j;
    else   g_midx[(b << 10) + (j - rank)] = j;   // masked list
    if (j >= cnt) g_idx[(b << 10) + j] = 0;
    if (j == 0) g_cnt[b] = cnt;
}

// -------------------- GEMM1c + masked-row fill on exit CTAs -----------------
// Compute CTAs (m0 < cnt): compacted hidden @ W1 + b1, RoPE -> g_qc/g_kc.
// Exit CTAs (m0 >= cnt): fill output rows of MASKED tokens with the exact
// constant pattern (n < m ? -2e12 : -1e12, both t slices) — overlaps the
// store-bound fill with the compute-bound GEMM (DRAM is ~2% busy here).
__global__ __launch_bounds__(256, 2) void gemm1_kernel(const float* __restrict__ b1v,
                                                       float* __restrict__ out)
{
    extern __shared__ char smem_raw[];
    char* base = (char*)(((uintptr_t)smem_raw + 1023) & ~(uintptr_t)1023);
    const uint32_t sb = smem_u32(base);
    const int tid = threadIdx.x, lane = tid & 31, wid = tid >> 5;
    const int wm = wid >> 2, wn = wid & 3;
    const int b = blockIdx.z;
    const int m0 = blockIdx.y * 128, n0 = blockIdx.x * 128;
    const int cnt = g_cnt[b];
    const int mtiles = (cnt + 127) >> 7;

    if ((int)blockIdx.y >= mtiles) {
        // ---- fill path: masked rows, constant pattern ----
        const int E = (8 - mtiles) * 16;
        const int eidx = ((int)blockIdx.y - mtiles) * 16 + (int)blockIdx.x;
        const int M = 1024 - cnt;
        const int r0 = eidx * M / E, r1 = (eidx + 1) * M / E;
        const int n4 = tid * 4;
        #pragma unroll 1
        for (int r = r0; r < r1; ++r) {
            const int m = g_midx[(b << 10) + r];
            float* o0 = out + ((size_t)(b * 2) << 20) + (size_t)m * 1024;
            float* o1 = o0 + (size_t)(1 << 20);
            float4 v;
            #pragma unroll
            for (int e = 0; e < 4; ++e)
                (&v.x)[e] = (n4 + e) < m ? -2e12f : -1e12f;
            stcs4(o0 + n4, v);
            stcs4(o1 + n4, v);
        }
        return;
    }

    const int lrow = tid >> 1, lc0 = (tid & 1) * 4;
    const int lorig = g_idx[(b << 10) + m0 + lrow];
    const __half* ap = g_hbf + ((size_t)(b << 10) + lorig) * 1024 + lc0 * 8;
    const __half* bp = g_w1t + (size_t)(n0 + lrow) * 1024 + lc0 * 8;

    float acc[4][4][4] = {};
    gemm_mainloop(ap, bp, sb, acc);

    float* Cb = (float*)base;      // [128][132]
    const int r0 = wm * 64 + (lane >> 2);
    const int c0l = wn * 32 + (lane & 3) * 2;
    #pragma unroll
    for (int mf = 0; mf < 4; ++mf)
        #pragma unroll
        for (int nf = 0; nf < 4; ++nf) {
            float* p = &Cb[(r0 + mf * 16) * 132 + c0l + nf * 8];
            *(float2*)p             = make_float2(acc[mf][nf][0], acc[mf][nf][1]);
            *(float2*)(p + 8 * 132) = make_float2(acc[mf][nf][2], acc[mf][nf][3]);
        }
    __syncthreads();

    // RoPE + scatter. Fixed quad per thread: __expf + b1 hoisted; __sincosf MUFU.
    const int quad = tid & 31;
    const int rgrp = tid >> 5;
    const int cb = n0 + quad * 4;
    const int ir = cb >> 2;
    const float inv = __expf(-(float)ir * (2.0f * 9.210340371976184f / 1024.0f));
    const float4 b1q = *(const float4*)&b1v[cb];

    #pragma unroll 1
    for (int it = 0; it < 16; ++it) {
        const int r = rgrp * 16 + it;
        float4 v = *(float4*)&Cb[r * 132 + quad * 4];
        const int j = m0 + r;                    // compact row
        const int l = g_idx[(b << 10) + j];      // original position
        float s, c;
        __sincosf((float)l * inv, &s, &c);
        float q0 = v.x + b1q.x;
        float k0 = v.y + b1q.y;
        float q1 = v.z + b1q.z;
        float k1 = v.w + b1q.w;
        __half2 qh = __floats2half2_rn(q0 * c - q1 * s, q1 * c + q0 * s);
        __half2 kh = __floats2half2_rn(k0 * c - k1 * s, k1 * c + k0 * s);
        const size_t dst = ((size_t)(b << 10) + j) * 1024 + (cb >> 1);
        *(uint32_t*)&g_qc[dst] = *reinterpret_cast<uint32_t*>(&qh);
        *(uint32_t*)&g_kc[dst] = *reinterpret_cast<uint32_t*>(&kh);
    }
}

// -------------------- GEMM2c: 64x64 tiles, dense triangular enumeration -----
__global__ __launch_bounds__(128, 4) void gemm2_kernel()
{
    extern __shared__ char smem_raw[];
    char* base = (char*)(((uintptr_t)smem_raw + 1023) & ~(uintptr_t)1023);
    const uint32_t sb = smem_u32(base);
    const int tid = threadIdx.x, lane = tid & 31, wid = tid >> 5;
    const int wm = wid >> 1, wn = wid & 1;
    const int b = blockIdx.y;

    const int t = blockIdx.x;
    int ni = 0;
    while ((ni + 1) * (ni + 2) / 2 <= t) ++ni;
    const int mi = t - ni * (ni + 1) / 2;
    const int m0 = mi * 64, n0 = ni * 64;
    const int c = g_cnt[b];
    if (m0 >= c || n0 >= c) return;

    const int lrow = tid >> 1, lc0 = (tid & 1) * 4;
    const __half* ap = g_qc + ((size_t)(b << 10) + m0 + lrow) * 1024 + lc0 * 8;
    const __half* bp = g_kc + ((size_t)(b << 10) + n0 + lrow) * 1024 + lc0 * 8;
    uint32_t soff[4];
    #pragma unroll
    for (int i = 0; i < 4; ++i) {
        uint32_t off = lrow * 128 + (lc0 + i) * 16;
        soff[i] = off ^ ((off >> 3) & 0x70);
    }
    uint32_t stA[3], stB[3];
    #pragma unroll
    for (int s = 0; s < 3; ++s) { stA[s] = sb + s * G2_STAGE; stB[s] = stA[s] + 8192; }

    #pragma unroll
    for (int tpre = 0; tpre < 2; ++tpre) {
        #pragma unroll
        for (int i = 0; i < 4; ++i) {
            cp16(stA[tpre] + soff[i], ap + tpre * 64 + i * 8);
            cp16(stB[tpre] + soff[i], bp + tpre * 64 + i * 8);
        }
        cp_commit();
    }

    const int lr = lane & 15, lhi = lane >> 4;
    const uint32_t xorterm = (uint32_t)(lr & 7) * 16;
    uint32_t aRow[2], bRow[2];
    #pragma unroll
    for (int mf = 0; mf < 2; ++mf) aRow[mf] = (uint32_t)(wm * 32 + mf * 16 + lr) * 128;
    #pragma unroll
    for (int nfp = 0; nfp < 2; ++nfp) bRow[nfp] = (uint32_t)(wn * 32 + nfp * 16 + lr) * 128;

    float acc[2][4][4] = {};

    #pragma unroll 1
    for (int kt = 0; kt < 16; ++kt) {
        if (kt == 15) asm volatile("cp.async.wait_group 0;" ::: "memory");
        else          asm volatile("cp.async.wait_group 1;" ::: "memory");
        __syncthreads();

        if (kt < 14) {
            const int tp = kt + 2;
            const int sl = tp - (tp / 3) * 3;
            #pragma unroll
            for (int i = 0; i < 4; ++i) {
                cp16(stA[sl] + soff[i], ap + tp * 64 + i * 8);
                cp16(stB[sl] + soff[i], bp + tp * 64 + i * 8);
            }
            cp_commit();
        }

        const int s = kt - (kt / 3) * 3;
        const uint32_t sA = stA[s], sB = stB[s];
        #pragma unroll
        for (int ks = 0; ks < 4; ++ks) {
            const uint32_t colbyte = ((uint32_t)(ks * 2 + lhi) * 16) ^ xorterm;
            uint32_t bfr[2][4];
            #pragma unroll
            for (int nfp = 0; nfp < 2; ++nfp) ldsm4(bfr[nfp], sB + bRow[nfp] + colbyte);
            #pragma unroll
            for (int mf = 0; mf < 2; ++mf) {
                uint32_t afr[4];
                ldsm4(afr, sA + aRow[mf] + colbyte);
                #pragma unroll
                for (int nf = 0; nf < 4; ++nf)
                    mma16816(acc[mf][nf], afr,
                             bfr[nf >> 1][nf & 1], bfr[nf >> 1][2 + (nf & 1)]);
            }
        }
    }

    #pragma unroll
    for (int mf = 0; mf < 2; ++mf)
        #pragma unroll
        for (int h = 0; h < 2; ++h) {
            const int Rl = wm * 32 + mf * 16 + (lane >> 2) + h * 8;
            float* orow = g_qk + ((size_t)b << 20) + (size_t)(m0 + Rl) * 1024 + n0;
            #pragma unroll
            for (int nf = 0; nf < 4; ++nf) {
                const int Cl = wn * 32 + nf * 8 + (lane & 3) * 2;
                *(float2*)(orow + Cl) =
                    make_float2(acc[mf][nf][h * 2], acc[mf][nf][h * 2 + 1]);
            }
        }
}

// -------------------- scatter: unmasked rows only (masked done by gemm1) ----
// case table (bit-exact vs fp32 reference, since |qk/32+biases| << ulp(1e12)):
//   unmasked & m<=n : qk/32 + bE + bO ; unmasked & m>n : -1e12f
//   masked   & m<=n : -1e12f          ; masked   & m>n : -2e12f
__global__ __launch_bounds__(256) void scatter_kernel(const int* __restrict__ tt,
                                                      float* __restrict__ out)
{
    const int b = blockIdx.y, m = blockIdx.x, tid = threadIdx.x;
    const int mr = tt[(b << 10) + m];
    float* o0 = out + ((size_t)(b * 2) << 20) + (size_t)m * 1024;
    float* o1 = o0 + (size_t)(1 << 20);
    const int n4 = tid * 4;

    if (mr == 0) {
        const int cnt = g_cnt[b];
        if (((cnt + 127) >> 7) < 8) return;      // filled by gemm1 exit CTAs
        float4 v;                                 // rare fallback (cnt > 896)
        #pragma unroll
        for (int e = 0; e < 4; ++e)
            (&v.x)[e] = (n4 + e) < m ? -2e12f : -1e12f;
        stcs4(o0 + n4, v);
        stcs4(o1 + n4, v);
        return;
    }

    const int rank_m = g_rank[(b << 10) + m];
    const float bo0 = g_bias[b * 4096 + 1024 + m];
    const float bo1 = g_bias[b * 4096 + 3072 + m];
    const float* qrow = g_qk + ((size_t)b << 20) + (size_t)rank_m * 1024;

    const int4  mc4 = *(const int4*)&tt[(b << 10) + n4];
    const int4  rk4 = *(const int4*)&g_rank[(b << 10) + n4];
    const float4 be0 = *(const float4*)&g_bias[b * 4096 + n4];
    const float4 be1 = *(const float4*)&g_bias[b * 4096 + 2048 + n4];

    float4 v0, v1;
    const int mcs[4] = {mc4.x, mc4.y, mc4.z, mc4.w};
    const int rks[4] = {rk4.x, rk4.y, rk4.z, rk4.w};
    #pragma unroll
    for (int e = 0; e < 4; ++e) {
        const int n = n4 + e;
        const bool um = (mcs[e] != 0);
        if (um && m <= n) {
            const float qk = __ldg(qrow + rks[e]);
            (&v0.x)[e] = fmaf(qk, 0.03125f, (&be0.x)[e]) + bo0;
            (&v1.x)[e] = fmaf(qk, 0.03125f, (&be1.x)[e]) + bo1;
        } else {
            const float f = (m > n && !um) ? -2e12f : -1e12f;
            (&v0.x)[e] = f;
            (&v1.x)[e] = f;
        }
    }
    stcs4(o0 + n4, v0);
    stcs4(o1 + n4, v1);
}

// -------------------- prep: fused hidden->fp16 convert + bias GEMV ----------
__global__ __launch_bounds__(256) void prep_hidden(const float* __restrict__ hidden,
                                                   const float* __restrict__ W2,
                                                   const float* __restrict__ b2)
{
    const int wid = threadIdx.x >> 5, lane = threadIdx.x & 31;
    const int row = blockIdx.x * 8 + wid;
    const float* h = hidden + (size_t)row * 1024;
    __half* o = g_hbf + (size_t)row * 1024;
    float a0 = 0.f, a1 = 0.f, a2 = 0.f, a3 = 0.f;
    #pragma unroll
    for (int i = 0; i < 8; ++i) {
        const int c4 = i * 32 + lane;
        float4 v = *(const float4*)&h[c4 * 4];
        __half2 h0 = __floats2half2_rn(v.x, v.y);
        __half2 h1 = __floats2half2_rn(v.z, v.w);
        uint2 st;
        st.x = *reinterpret_cast<uint32_t*>(&h0);
        st.y = *reinterpret_cast<uint32_t*>(&h1);
        *(uint2*)&o[c4 * 4] = st;
        const int k = c4 * 4;
        float4 w0 = *(const float4*)&W2[(k + 0) * 4];
        float4 w1 = *(const float4*)&W2[(k + 1) * 4];
        float4 w2 = *(const float4*)&W2[(k + 2) * 4];
        float4 w3 = *(const float4*)&W2[(k + 3) * 4];
        a0 += v.x * w0.x + v.y * w1.x + v.z * w2.x + v.w * w3.x;
        a1 += v.x * w0.y + v.y * w1.y + v.z * w2.y + v.w * w3.y;
        a2 += v.x * w0.z + v.y * w1.z + v.z * w2.z + v.w * w3.z;
        a3 += v.x * w0.w + v.y * w1.w + v.z * w2.w + v.w * w3.w;
    }
    #pragma unroll
    for (int off = 16; off > 0; off >>= 1) {
        a0 += __shfl_xor_sync(0xFFFFFFFF, a0, off);
        a1 += __shfl_xor_sync(0xFFFFFFFF, a1, off);
        a2 += __shfl_xor_sync(0xFFFFFFFF, a2, off);
        a3 += __shfl_xor_sync(0xFFFFFFFF, a3, off);
    }
    if (lane == 0) {
        const int bb = row >> 10, l = row & 1023;
        float* bp = g_bias + (size_t)bb * 4096 + l;
        bp[0]    = (a0 + b2[0]) * 0.5f;
        bp[1024] = (a1 + b2[1]) * 0.5f;
        bp[2048] = (a2 + b2[2]) * 0.5f;
        bp[3072] = (a3 + b2[3]) * 0.5f;
    }
}

__global__ __launch_bounds__(256) void transpose_w1(const float* __restrict__ W1)
{
    __shared__ float tile[32][33];
    const int tx = threadIdx.x & 31, ty = threadIdx.x >> 5;
    const int nb = blockIdx.x * 32, kb = blockIdx.y * 32;
    #pragma unroll
    for (int i = 0; i < 4; ++i)
        tile[ty + i * 8][tx] = W1[(size_t)(kb + ty + i * 8) * 2048 + nb + tx];
    __syncthreads();
    #pragma unroll
    for (int i = 0; i < 4; ++i)
        g_w1t[(size_t)(nb + ty + i * 8) * 1024 + kb + tx] = __float2half_rn(tile[tx][ty + i * 8]);
}

// -------------------- launch --------------------
extern "C" void kernel_launch(void* const* d_in, const int* in_sizes, int n_in,
                              void* d_out, int out_size)
{
    const float* hidden = (const float*)d_in[0];
    const int*   tt     = (const int*)d_in[1];
    const float* W1     = (const float*)d_in[2];
    const float* b1     = (const float*)d_in[3];
    const float* W2     = (const float*)d_in[4];
    const float* b2     = (const float*)d_in[5];
    float* out = (float*)d_out;

    cudaFuncSetAttribute(gemm1_kernel, cudaFuncAttributeMaxDynamicSharedMemorySize, DYN_SMEM);
    cudaFuncSetAttribute(gemm2_kernel, cudaFuncAttributeMaxDynamicSharedMemorySize, DYN_SMEM2);

    compact_kernel<<<BATCH, 1024>>>(tt);
    prep_hidden<<<2048, 256>>>(hidden, W2, b2);
    transpose_w1<<<dim3(64, 32), dim3(256)>>>(W1);

    dim3 g1(16, 8, BATCH);            // compute tiles + masked-row fill CTAs
    gemm1_kernel<<<g1, 256, DYN_SMEM>>>(b1, out);

    dim3 g2(45, BATCH);               // triangular 64x64 tiles (exit on cnt)
    gemm2_kernel<<<g2, 128, DYN_SMEM2>>>();

    dim3 gs(LSEQ, BATCH);             // unmasked rows (+ rare fallback fill)
    scatter_kernel<<<gs, 256>>>(tt, out);
}